// round 5
// baseline (speedup 1.0000x reference)
#include <cuda_runtime.h>

// ---------------- problem constants ----------------
#define BB    64
#define CC    3
#define NWIN  232
#define TT    8
#define CHUNK 29
#define DP    14
#define HP    16
#define WPOOL 16
#define NN    42            // CC*DP
#define FF    256           // HP*WPOOL
#define H0    256
#define H1    128
#define NCLS  6
#define R1    (TT*BB*NN)    // 21504 rows of cur_in_all
#define R2    (BB*NN)       // 2688 rows per timestep
#define NBLK  148           // persistent-shaped grid for step kernel

typedef unsigned long long ull;

// ---------------- scratch (device globals; no mallocs allowed) -------------
__device__ float g_pr[(size_t)R1 * FF];       // pooled activations
__device__ float g_cur[(size_t)R1 * H0];      // cur_in_all (fc_in output)
__device__ float g_mem_in[(size_t)R2 * H0];
__device__ float g_mem_hid[(size_t)R2 * H1];
__device__ float g_mem_out[BB * NCLS];
__device__ float g_partial[(size_t)R2 * NCLS];

// ---------------- packed f32x2 helpers ----------------
__device__ __forceinline__ ull fma2(ull a, ull b, ull c) {
    asm("fma.rn.f32x2 %0, %1, %2, %0;" : "+l"(c) : "l"(a), "l"(b));
    return c;
}
__device__ __forceinline__ ull add2(ull a, ull b) {
    ull d;
    asm("add.rn.f32x2 %0, %1, %2;" : "=l"(d) : "l"(a), "l"(b));
    return d;
}
__device__ __forceinline__ ull dup2(float a) {
    unsigned u = __float_as_uint(a);
    ull d;
    asm("mov.b64 %0, {%1, %2};" : "=l"(d) : "r"(u), "r"(u));
    return d;
}

union F4U { float4 f; ull u[2]; float s[4]; };
union F2U { float2 f; ull u; float s[2]; };

__device__ __forceinline__ float clamp01(float v) {
    return fminf(fmaxf(v, 0.f), 1.f);
}

// ============================================================
// Kernel 1: avg-pool3d (2,2,2)/(2,2,2) VALID, fused reshape to (R1, 256)
// grid = R1 blocks, 256 threads; one output per thread.
// ============================================================
__global__ __launch_bounds__(256) void pool_kernel(const float* __restrict__ x) {
    int row = blockIdx.x;
    int f   = threadIdx.x;

    int t   = row / (BB * NN);
    int rem = row % (BB * NN);
    int b   = rem / NN;
    int n   = rem % NN;
    int c   = n / DP;
    int d   = n % DP;
    int hp  = f >> 4;
    int wp  = f & 15;

    const float2* x2 = (const float2*)x;
    long long base = ((long long)(b * CC + c) * NWIN + t * CHUNK + 2 * d) * 32;

    float s = 0.f;
    #pragma unroll
    for (int kd = 0; kd < 2; kd++) {
        #pragma unroll
        for (int kh = 0; kh < 2; kh++) {
            float2 v = x2[(base + (long long)kd * 32 + 2 * hp + kh) * 16 + wp];
            s += v.x + v.y;
        }
    }
    g_pr[(size_t)row * FF + f] = s * 0.125f;
}

// ============================================================
// Kernel 2: cur_in_all = pr @ W_in^T + b_in   (M=21504, N=256, K=256), fp32
// classic SGEMM, BM=BN=128, BK=16, 8x8 microtile, packed f32x2 FMAs
// ============================================================
__global__ __launch_bounds__(256) void gemm1_kernel(const float* __restrict__ Win,
                                                    const float* __restrict__ bin) {
    __shared__ float As[16 * 132];
    __shared__ float Bs[16 * 132];

    int tid = threadIdx.x;
    int m0 = blockIdx.x * 128;
    int n0 = blockIdx.y * 128;
    int tx = tid & 15;     // n-group
    int ty = tid >> 4;     // m-group

    ull acc[8][4];
    #pragma unroll
    for (int m = 0; m < 8; m++)
        #pragma unroll
        for (int nn = 0; nn < 4; nn++) acc[m][nn] = 0ull;

    for (int k0 = 0; k0 < H0; k0 += 16) {
        #pragma unroll
        for (int i = 0; i < 2; i++) {
            int idx = tid + i * 256;
            int r = idx >> 2;
            int c4 = (idx & 3) * 4;
            float4 va = *(const float4*)(g_pr + (size_t)(m0 + r) * FF + k0 + c4);
            As[(c4 + 0) * 132 + r] = va.x;
            As[(c4 + 1) * 132 + r] = va.y;
            As[(c4 + 2) * 132 + r] = va.z;
            As[(c4 + 3) * 132 + r] = va.w;
            float4 vb = *(const float4*)(Win + (size_t)(n0 + r) * H0 + k0 + c4);
            Bs[(c4 + 0) * 132 + r] = vb.x;
            Bs[(c4 + 1) * 132 + r] = vb.y;
            Bs[(c4 + 2) * 132 + r] = vb.z;
            Bs[(c4 + 3) * 132 + r] = vb.w;
        }
        __syncthreads();

        #pragma unroll
        for (int kk = 0; kk < 16; kk++) {
            F4U a0, a1, b0, b1;
            a0.f = *(const float4*)&As[kk * 132 + ty * 8];
            a1.f = *(const float4*)&As[kk * 132 + ty * 8 + 4];
            b0.f = *(const float4*)&Bs[kk * 132 + tx * 8];
            b1.f = *(const float4*)&Bs[kk * 132 + tx * 8 + 4];
            ull bp[4] = { b0.u[0], b0.u[1], b1.u[0], b1.u[1] };
            float av[8] = { a0.s[0], a0.s[1], a0.s[2], a0.s[3],
                            a1.s[0], a1.s[1], a1.s[2], a1.s[3] };
            #pragma unroll
            for (int m = 0; m < 8; m++) {
                ull ad = dup2(av[m]);
                #pragma unroll
                for (int nn = 0; nn < 4; nn++)
                    acc[m][nn] = fma2(ad, bp[nn], acc[m][nn]);
            }
        }
        __syncthreads();
    }

    F4U bi0, bi1;
    bi0.f = *(const float4*)(bin + n0 + tx * 8);
    bi1.f = *(const float4*)(bin + n0 + tx * 8 + 4);
    ull bp[4] = { bi0.u[0], bi0.u[1], bi1.u[0], bi1.u[1] };

    #pragma unroll
    for (int m = 0; m < 8; m++) {
        F4U o0, o1;
        o0.u[0] = add2(acc[m][0], bp[0]);
        o0.u[1] = add2(acc[m][1], bp[1]);
        o1.u[0] = add2(acc[m][2], bp[2]);
        o1.u[1] = add2(acc[m][3], bp[3]);
        float* outp = g_cur + (size_t)(m0 + ty * 8 + m) * H0 + n0 + tx * 8;
        *(float4*)outp = o0.f;
        *(float4*)(outp + 4) = o1.f;
    }
}

// ============================================================
// Kernel 3 (per step): fused LIF1 + spike-compacted hidden GEMM + LIF2
//                      + per-row readout partials
// grid = 148 blocks x 256 threads; each block owns 18-19 (b,n) rows.
// W_hid cached in smem, transposed (k-major) for pair-wide adds.
// Spikes are exactly {0,1}: cur_hid = b_hid + sum of W_hid columns at
// active k  -> multiply-free, deterministic (ascending-k order).
// ============================================================
#define SROWS 20
#define WROW  130                       // 128 + pad (even, keeps float2 align)
#define SMEM_W_BYTES     (257 * WROW * 4)           // 133640 (row 256 = zeros)
#define SMEM_SPK2_OFF    SMEM_W_BYTES               // 20*128 floats
#define SMEM_LST_OFF     (SMEM_SPK2_OFF + SROWS * H1 * 4)   // 20*256 ushort
#define SMEM_CNT_OFF     (SMEM_LST_OFF + SROWS * 256 * 2)   // 20 ints
#define STEP_SMEM        (SMEM_CNT_OFF + SROWS * 4)

__global__ __launch_bounds__(256) void step_kernel(
    const float* __restrict__ W_hid, const float* __restrict__ b_hid,
    const float* __restrict__ beta_in, const float* __restrict__ thr_in,
    const float* __restrict__ beta_hid, const float* __restrict__ thr_hid,
    const float* __restrict__ W_out, int t)
{
    extern __shared__ char smem[];
    float*          sW    = (float*)smem;
    float*          sSpk2 = (float*)(smem + SMEM_SPK2_OFF);
    unsigned short* sLst  = (unsigned short*)(smem + SMEM_LST_OFF);
    int*            sCnt  = (int*)(smem + SMEM_CNT_OFF);

    int tid  = threadIdx.x;
    int lane = tid & 31;
    int warp = tid >> 5;
    int r0 = (int)(((long long)blockIdx.x * R2) / NBLK);
    int r1 = (int)(((long long)(blockIdx.x + 1) * R2) / NBLK);

    // ---- phase 0: stage W_hid transposed (k-major) + zero sentinel row ----
    #pragma unroll 4
    for (int g = 0; g < H1; g++)
        sW[tid * WROW + g] = W_hid[g * H0 + tid];   // tid == k
    if (tid < H1) sW[256 * WROW + tid] = 0.f;

    // ---- phase 1: LIF1 + warp-ballot compaction of active h per row ----
    const float* cur_t = g_cur + (size_t)t * R2 * H0;
    unsigned lmask = (1u << lane) - 1u;
    for (int rl = warp; rl < SROWS; rl += 8) {
        int row = r0 + rl;
        if (row < r1) {
            int cnt = 0;
            unsigned short* lst = sLst + rl * 256;
            const float* curp = cur_t + (size_t)row * H0;
            float* memp = g_mem_in + (size_t)row * H0;
            #pragma unroll
            for (int kb = 0; kb < 8; kb++) {
                int k = kb * 32 + lane;
                float thr  = thr_in[k];
                float beta = clamp01(beta_in[k]);
                float mem  = (t == 0) ? 0.f : memp[k];
                float cur  = curp[k];
                float rst  = (mem > thr) ? thr : 0.f;
                mem = fmaf(beta, mem, cur) - rst;
                memp[k] = mem;
                int s = (mem - thr > 0.f) ? 1 : 0;
                unsigned bal = __ballot_sync(0xffffffffu, s);
                if (s) lst[cnt + __popc(bal & lmask)] = (unsigned short)k;
                cnt += __popc(bal);
            }
            int cnt4 = (cnt + 3) & ~3;
            if (lane < cnt4 - cnt) lst[cnt + lane] = 256;   // zero-row sentinel
            if (lane == 0) sCnt[rl] = cnt4;
        } else if (lane == 0) {
            sCnt[rl] = 0;
        }
    }
    __syncthreads();

    // ---- phase 2+3: hidden current (compacted adds) + LIF2 ----
    int j = tid & 63;       // g-pair
    int q = tid >> 6;       // row-within-chunk
    const ull* sW2 = (const ull*)sW;

    F2U bh;  bh.f  = *(const float2*)(b_hid   + 2 * j);
    float2 bhf     = *(const float2*)(beta_hid + 2 * j);
    float betx = clamp01(bhf.x), bety = clamp01(bhf.y);
    float2 thh     = *(const float2*)(thr_hid + 2 * j);

    #pragma unroll
    for (int c = 0; c < 5; c++) {
        int rl = c * 4 + q;
        int cnt4 = sCnt[rl];
        const unsigned short* lst = sLst + rl * 256;
        ull acc0 = bh.u;
        ull acc1 = 0ull;
        for (int i = 0; i < cnt4; i += 4) {
            ushort4 kk = *(const ushort4*)(lst + i);
            acc0 = add2(acc0, sW2[(int)kk.x * 65 + j]);
            acc1 = add2(acc1, sW2[(int)kk.y * 65 + j]);
            acc0 = add2(acc0, sW2[(int)kk.z * 65 + j]);
            acc1 = add2(acc1, sW2[(int)kk.w * 65 + j]);
        }
        ull accs = add2(acc0, acc1);

        int row = r0 + rl;
        if (row < r1) {
            F2U a; a.u = accs;
            float2 mem = (t == 0) ? make_float2(0.f, 0.f)
                                  : *(const float2*)(g_mem_hid + (size_t)row * H1 + 2 * j);
            float rx = (mem.x > thh.x) ? thh.x : 0.f;
            float ry = (mem.y > thh.y) ? thh.y : 0.f;
            mem.x = fmaf(betx, mem.x, a.s[0]) - rx;
            mem.y = fmaf(bety, mem.y, a.s[1]) - ry;
            *(float2*)(g_mem_hid + (size_t)row * H1 + 2 * j) = mem;
            float2 sp;
            sp.x = (mem.x - thh.x > 0.f) ? 1.f : 0.f;
            sp.y = (mem.y - thh.y > 0.f) ? 1.f : 0.f;
            *(float2*)(sSpk2 + rl * H1 + 2 * j) = sp;
        }
    }
    __syncthreads();

    // ---- phase 4: per-row readout partials (warp tree reduce; fixed order) ----
    for (int rl = warp; rl < SROWS; rl += 8) {
        int row = r0 + rl;
        if (row >= r1) continue;
        int n = row % NN;
        const float* wo = W_out + n * H1;
        float sv[4];
        #pragma unroll
        for (int gi = 0; gi < 4; gi++) sv[gi] = sSpk2[rl * H1 + gi * 32 + lane];
        #pragma unroll
        for (int cls = 0; cls < NCLS; cls++) {
            float p = 0.f;
            #pragma unroll
            for (int gi = 0; gi < 4; gi++)
                p = fmaf(wo[cls * (NN * H1) + gi * 32 + lane], sv[gi], p);
            #pragma unroll
            for (int off = 16; off; off >>= 1)
                p += __shfl_down_sync(0xffffffffu, p, off);
            if (lane == 0) g_partial[(size_t)row * NCLS + cls] = p;
        }
    }
}

// ============================================================
// Kernel 4 (per step): deterministic readout reduction + output LIF
// ============================================================
__global__ __launch_bounds__(BB * NCLS) void out_kernel(
    const float* __restrict__ b_out, const float* __restrict__ beta_out,
    float* __restrict__ out, int t)
{
    int tid = threadIdx.x;                 // 0..383
    int b = tid / NCLS, cls = tid % NCLS;
    float s = b_out[cls];
    const float* pp = g_partial + (size_t)b * (NN * NCLS) + cls;
    #pragma unroll
    for (int n = 0; n < NN; n++) s += pp[n * NCLS];

    float mem  = (t == 0) ? 0.f : g_mem_out[tid];
    float beta = clamp01(beta_out[cls]);
    float rst  = (mem > 1.f) ? 1.f : 0.f;
    mem = fmaf(beta, mem, s) - rst;
    g_mem_out[tid] = mem;
    out[t * (BB * NCLS) + tid] = (mem - 1.f > 0.f) ? 1.f : 0.f;
}

// ============================================================
// launch
// ============================================================
extern "C" void kernel_launch(void* const* d_in, const int* in_sizes, int n_in,
                              void* d_out, int out_size) {
    (void)in_sizes; (void)n_in; (void)out_size;
    const float* x        = (const float*)d_in[0];
    const float* W_in     = (const float*)d_in[1];
    const float* b_in     = (const float*)d_in[2];
    const float* W_hid    = (const float*)d_in[3];
    const float* b_hid    = (const float*)d_in[4];
    const float* W_out    = (const float*)d_in[5];
    const float* b_out    = (const float*)d_in[6];
    const float* beta_in  = (const float*)d_in[7];
    const float* thr_in   = (const float*)d_in[8];
    const float* beta_hid = (const float*)d_in[9];
    const float* thr_hid  = (const float*)d_in[10];
    const float* beta_out = (const float*)d_in[11];
    float* out = (float*)d_out;

    pool_kernel<<<R1, 256>>>(x);
    gemm1_kernel<<<dim3(R1 / 128, H0 / 128), 256>>>(W_in, b_in);

    cudaFuncSetAttribute(step_kernel,
                         cudaFuncAttributeMaxDynamicSharedMemorySize, STEP_SMEM);
    for (int t = 0; t < TT; t++) {
        step_kernel<<<NBLK, 256, STEP_SMEM>>>(W_hid, b_hid, beta_in, thr_in,
                                              beta_hid, thr_hid, W_out, t);
        out_kernel<<<1, BB * NCLS>>>(b_out, beta_out, out, t);
    }
}

// round 6
// speedup vs baseline: 1.6133x; 1.6133x over previous
#include <cuda_runtime.h>

// ---------------- problem constants ----------------
#define BB    64
#define CC    3
#define NWIN  232
#define TT    8
#define CHUNK 29
#define DP    14
#define HP    16
#define WPOOL 16
#define NN    42            // CC*DP
#define FF    256           // HP*WPOOL
#define H0    256
#define H1    128
#define NCLS  6
#define R1    (TT*BB*NN)    // 21504 rows of cur_in_all
#define R2    (BB*NN)       // 2688 rows per timestep
#define NBLK  148           // persistent-shaped grid (one wave, 1 blk/SM)

typedef unsigned long long ull;

// ---------------- scratch (device globals; no mallocs allowed) -------------
__device__ float g_pr[(size_t)R1 * FF];             // pooled activations
__device__ float g_cur[(size_t)R1 * H0];            // cur_in_all (fc_in output)
__device__ float g_partial[(size_t)TT * R2 * NCLS]; // readout partials per step

// ---------------- packed f32x2 helpers ----------------
__device__ __forceinline__ ull fma2(ull a, ull b, ull c) {
    asm("fma.rn.f32x2 %0, %1, %2, %0;" : "+l"(c) : "l"(a), "l"(b));
    return c;
}
__device__ __forceinline__ ull add2(ull a, ull b) {
    ull d;
    asm("add.rn.f32x2 %0, %1, %2;" : "=l"(d) : "l"(a), "l"(b));
    return d;
}
__device__ __forceinline__ ull dup2(float a) {
    unsigned u = __float_as_uint(a);
    ull d;
    asm("mov.b64 %0, {%1, %2};" : "=l"(d) : "r"(u), "r"(u));
    return d;
}

union F4U { float4 f; ull u[2]; float s[4]; };
union F2U { float2 f; ull u; float s[2]; };

__device__ __forceinline__ float clamp01(float v) {
    return fminf(fmaxf(v, 0.f), 1.f);
}

// ============================================================
// Kernel 1: avg-pool3d (2,2,2)/(2,2,2) VALID, fused reshape to (R1, 256)
// ============================================================
__global__ __launch_bounds__(256) void pool_kernel(const float* __restrict__ x) {
    int row = blockIdx.x;
    int f   = threadIdx.x;

    int t   = row / (BB * NN);
    int rem = row % (BB * NN);
    int b   = rem / NN;
    int n   = rem % NN;
    int c   = n / DP;
    int d   = n % DP;
    int hp  = f >> 4;
    int wp  = f & 15;

    const float2* x2 = (const float2*)x;
    long long base = ((long long)(b * CC + c) * NWIN + t * CHUNK + 2 * d) * 32;

    float s = 0.f;
    #pragma unroll
    for (int kd = 0; kd < 2; kd++) {
        #pragma unroll
        for (int kh = 0; kh < 2; kh++) {
            float2 v = x2[(base + (long long)kd * 32 + 2 * hp + kh) * 16 + wp];
            s += v.x + v.y;
        }
    }
    g_pr[(size_t)row * FF + f] = s * 0.125f;
}

// ============================================================
// Kernel 2: cur_in_all = pr @ W_in^T + b_in   (M=21504, N=256, K=256), fp32
// ============================================================
__global__ __launch_bounds__(256) void gemm1_kernel(const float* __restrict__ Win,
                                                    const float* __restrict__ bin) {
    __shared__ float As[16 * 132];
    __shared__ float Bs[16 * 132];

    int tid = threadIdx.x;
    int m0 = blockIdx.x * 128;
    int n0 = blockIdx.y * 128;
    int tx = tid & 15;
    int ty = tid >> 4;

    ull acc[8][4];
    #pragma unroll
    for (int m = 0; m < 8; m++)
        #pragma unroll
        for (int nn = 0; nn < 4; nn++) acc[m][nn] = 0ull;

    for (int k0 = 0; k0 < H0; k0 += 16) {
        #pragma unroll
        for (int i = 0; i < 2; i++) {
            int idx = tid + i * 256;
            int r = idx >> 2;
            int c4 = (idx & 3) * 4;
            float4 va = *(const float4*)(g_pr + (size_t)(m0 + r) * FF + k0 + c4);
            As[(c4 + 0) * 132 + r] = va.x;
            As[(c4 + 1) * 132 + r] = va.y;
            As[(c4 + 2) * 132 + r] = va.z;
            As[(c4 + 3) * 132 + r] = va.w;
            float4 vb = *(const float4*)(Win + (size_t)(n0 + r) * H0 + k0 + c4);
            Bs[(c4 + 0) * 132 + r] = vb.x;
            Bs[(c4 + 1) * 132 + r] = vb.y;
            Bs[(c4 + 2) * 132 + r] = vb.z;
            Bs[(c4 + 3) * 132 + r] = vb.w;
        }
        __syncthreads();

        #pragma unroll
        for (int kk = 0; kk < 16; kk++) {
            F4U a0, a1, b0, b1;
            a0.f = *(const float4*)&As[kk * 132 + ty * 8];
            a1.f = *(const float4*)&As[kk * 132 + ty * 8 + 4];
            b0.f = *(const float4*)&Bs[kk * 132 + tx * 8];
            b1.f = *(const float4*)&Bs[kk * 132 + tx * 8 + 4];
            ull bp[4] = { b0.u[0], b0.u[1], b1.u[0], b1.u[1] };
            float av[8] = { a0.s[0], a0.s[1], a0.s[2], a0.s[3],
                            a1.s[0], a1.s[1], a1.s[2], a1.s[3] };
            #pragma unroll
            for (int m = 0; m < 8; m++) {
                ull ad = dup2(av[m]);
                #pragma unroll
                for (int nn = 0; nn < 4; nn++)
                    acc[m][nn] = fma2(ad, bp[nn], acc[m][nn]);
            }
        }
        __syncthreads();
    }

    F4U bi0, bi1;
    bi0.f = *(const float4*)(bin + n0 + tx * 8);
    bi1.f = *(const float4*)(bin + n0 + tx * 8 + 4);
    ull bp[4] = { bi0.u[0], bi0.u[1], bi1.u[0], bi1.u[1] };

    #pragma unroll
    for (int m = 0; m < 8; m++) {
        F4U o0, o1;
        o0.u[0] = add2(acc[m][0], bp[0]);
        o0.u[1] = add2(acc[m][1], bp[1]);
        o1.u[0] = add2(acc[m][2], bp[2]);
        o1.u[1] = add2(acc[m][3], bp[3]);
        float* outp = g_cur + (size_t)(m0 + ty * 8 + m) * H0 + n0 + tx * 8;
        *(float4*)outp = o0.f;
        *(float4*)(outp + 4) = o1.f;
    }
}

// ============================================================
// Kernel 3: ALL 8 timesteps fused in one persistent kernel.
// Recurrence is block-local: each block owns its 18-19 (b,n) rows; the
// membranes live in REGISTERS across all steps (no global traffic), and
// W_hid is staged into smem exactly once.
// ============================================================
#define SROWS 20
#define WROW  130
#define SMEM_W_BYTES     (257 * WROW * 4)
#define SMEM_SPK2_OFF    SMEM_W_BYTES
#define SMEM_LST_OFF     (SMEM_SPK2_OFF + SROWS * H1 * 4)
#define SMEM_CNT_OFF     (SMEM_LST_OFF + SROWS * 256 * 2)
#define STEP_SMEM        (SMEM_CNT_OFF + SROWS * 4)

__global__ __launch_bounds__(256) void step_all_kernel(
    const float* __restrict__ W_hid, const float* __restrict__ b_hid,
    const float* __restrict__ beta_in, const float* __restrict__ thr_in,
    const float* __restrict__ beta_hid, const float* __restrict__ thr_hid,
    const float* __restrict__ W_out)
{
    extern __shared__ char smem[];
    float*          sW    = (float*)smem;
    float*          sSpk2 = (float*)(smem + SMEM_SPK2_OFF);
    unsigned short* sLst  = (unsigned short*)(smem + SMEM_LST_OFF);
    int*            sCnt  = (int*)(smem + SMEM_CNT_OFF);

    int tid  = threadIdx.x;
    int lane = tid & 31;
    int warp = tid >> 5;
    int r0 = (int)(((long long)blockIdx.x * R2) / NBLK);
    int r1 = (int)(((long long)(blockIdx.x + 1) * R2) / NBLK);

    // ---- stage W_hid transposed (k-major) + zero sentinel row, ONCE ----
    #pragma unroll 4
    for (int g = 0; g < H1; g++)
        sW[tid * WROW + g] = W_hid[g * H0 + tid];   // tid == k
    if (tid < H1) sW[256 * WROW + tid] = 0.f;

    // ---- hoisted LIF1 params + register-resident mem_in ----
    float thrA[8], betA[8];
    #pragma unroll
    for (int kb = 0; kb < 8; kb++) {
        int k = kb * 32 + lane;
        thrA[kb] = thr_in[k];
        betA[kb] = clamp01(beta_in[k]);
    }
    float memA[3][8];
    #pragma unroll
    for (int ri = 0; ri < 3; ri++)
        #pragma unroll
        for (int kb = 0; kb < 8; kb++) memA[ri][kb] = 0.f;

    // ---- hoisted LIF2 params + register-resident mem_hid ----
    int j = tid & 63;       // g-pair
    int q = tid >> 6;       // row-within-chunk
    const ull* sW2 = (const ull*)sW;
    F2U bh;  bh.f  = *(const float2*)(b_hid    + 2 * j);
    float2 bhf     = *(const float2*)(beta_hid + 2 * j);
    float betx = clamp01(bhf.x), bety = clamp01(bhf.y);
    float2 thh     = *(const float2*)(thr_hid  + 2 * j);
    float2 memh[5];
    #pragma unroll
    for (int c = 0; c < 5; c++) memh[c] = make_float2(0.f, 0.f);

    unsigned lmask = (1u << lane) - 1u;
    __syncthreads();

    for (int t = 0; t < TT; t++) {
        // ---- phase 1: LIF1 + warp-ballot compaction of active h per row ----
        #pragma unroll
        for (int ri = 0; ri < 3; ri++) {
            int rl = warp + ri * 8;
            if (rl < SROWS) {
                int row = r0 + rl;
                if (row < r1) {
                    int cnt = 0;
                    unsigned short* lst = sLst + rl * 256;
                    const float* curp = g_cur + ((size_t)t * R2 + row) * H0;
                    #pragma unroll
                    for (int kb = 0; kb < 8; kb++) {
                        float mem = memA[ri][kb];
                        float cur = curp[kb * 32 + lane];
                        float rst = (mem > thrA[kb]) ? thrA[kb] : 0.f;
                        mem = fmaf(betA[kb], mem, cur) - rst;
                        memA[ri][kb] = mem;
                        int s = (mem - thrA[kb] > 0.f) ? 1 : 0;
                        unsigned bal = __ballot_sync(0xffffffffu, s);
                        if (s) lst[cnt + __popc(bal & lmask)] =
                                   (unsigned short)(kb * 32 + lane);
                        cnt += __popc(bal);
                    }
                    int cnt4 = (cnt + 3) & ~3;
                    if (lane < cnt4 - cnt) lst[cnt + lane] = 256;  // zero-row pad
                    if (lane == 0) sCnt[rl] = cnt4;
                } else if (lane == 0) {
                    sCnt[rl] = 0;
                }
            }
        }
        __syncthreads();

        // ---- phase 2+3: hidden current (compacted adds) + LIF2 ----
        #pragma unroll
        for (int c = 0; c < 5; c++) {
            int rl = c * 4 + q;
            int cnt4 = sCnt[rl];
            const unsigned short* lst = sLst + rl * 256;
            ull acc0 = bh.u;
            ull acc1 = 0ull;
            for (int i = 0; i < cnt4; i += 4) {
                ushort4 kk = *(const ushort4*)(lst + i);
                acc0 = add2(acc0, sW2[(int)kk.x * 65 + j]);
                acc1 = add2(acc1, sW2[(int)kk.y * 65 + j]);
                acc0 = add2(acc0, sW2[(int)kk.z * 65 + j]);
                acc1 = add2(acc1, sW2[(int)kk.w * 65 + j]);
            }
            ull accs = add2(acc0, acc1);

            int row = r0 + rl;
            if (row < r1) {
                F2U a; a.u = accs;
                float2 mem = memh[c];
                float rx = (mem.x > thh.x) ? thh.x : 0.f;
                float ry = (mem.y > thh.y) ? thh.y : 0.f;
                mem.x = fmaf(betx, mem.x, a.s[0]) - rx;
                mem.y = fmaf(bety, mem.y, a.s[1]) - ry;
                memh[c] = mem;
                float2 sp;
                sp.x = (mem.x - thh.x > 0.f) ? 1.f : 0.f;
                sp.y = (mem.y - thh.y > 0.f) ? 1.f : 0.f;
                *(float2*)(sSpk2 + rl * H1 + 2 * j) = sp;
            }
        }
        __syncthreads();

        // ---- phase 4: per-row readout partials (fixed-order reduce) ----
        // (No trailing sync needed: next phase 1 touches only sLst/sCnt/g_cur,
        //  disjoint from sSpk2 read here; next phase 2 is behind a sync.)
        for (int rl = warp; rl < SROWS; rl += 8) {
            int row = r0 + rl;
            if (row >= r1) continue;
            int n = row % NN;
            const float* wo = W_out + n * H1;
            float sv[4];
            #pragma unroll
            for (int gi = 0; gi < 4; gi++) sv[gi] = sSpk2[rl * H1 + gi * 32 + lane];
            #pragma unroll
            for (int cls = 0; cls < NCLS; cls++) {
                float p = 0.f;
                #pragma unroll
                for (int gi = 0; gi < 4; gi++)
                    p = fmaf(wo[cls * (NN * H1) + gi * 32 + lane], sv[gi], p);
                #pragma unroll
                for (int off = 16; off; off >>= 1)
                    p += __shfl_down_sync(0xffffffffu, p, off);
                if (lane == 0)
                    g_partial[((size_t)t * R2 + row) * NCLS + cls] = p;
            }
        }
    }
}

// ============================================================
// Kernel 4: all 8 output-LIF steps in one launch. Batch-load the 8
// partial sums first (independent loads -> high MLP), then run the
// trivial LIF chain in registers. Summation order matches R5 exactly.
// ============================================================
__global__ __launch_bounds__(BB * NCLS) void out_all_kernel(
    const float* __restrict__ b_out, const float* __restrict__ beta_out,
    float* __restrict__ out)
{
    int tid = threadIdx.x;                 // 0..383
    int b = tid / NCLS, cls = tid % NCLS;
    float bo   = b_out[cls];
    float beta = clamp01(beta_out[cls]);

    float sums[TT];
    #pragma unroll
    for (int t = 0; t < TT; t++) {
        float s = bo;
        const float* pp = g_partial + ((size_t)t * R2 + (size_t)b * NN) * NCLS + cls;
        #pragma unroll
        for (int n = 0; n < NN; n++) s += pp[n * NCLS];
        sums[t] = s;
    }

    float mem = 0.f;
    #pragma unroll
    for (int t = 0; t < TT; t++) {
        float rst = (mem > 1.f) ? 1.f : 0.f;
        mem = fmaf(beta, mem, sums[t]) - rst;
        out[t * (BB * NCLS) + tid] = (mem - 1.f > 0.f) ? 1.f : 0.f;
    }
}

// ============================================================
// launch
// ============================================================
extern "C" void kernel_launch(void* const* d_in, const int* in_sizes, int n_in,
                              void* d_out, int out_size) {
    (void)in_sizes; (void)n_in; (void)out_size;
    const float* x        = (const float*)d_in[0];
    const float* W_in     = (const float*)d_in[1];
    const float* b_in     = (const float*)d_in[2];
    const float* W_hid    = (const float*)d_in[3];
    const float* b_hid    = (const float*)d_in[4];
    const float* W_out    = (const float*)d_in[5];
    const float* b_out    = (const float*)d_in[6];
    const float* beta_in  = (const float*)d_in[7];
    const float* thr_in   = (const float*)d_in[8];
    const float* beta_hid = (const float*)d_in[9];
    const float* thr_hid  = (const float*)d_in[10];
    const float* beta_out = (const float*)d_in[11];
    float* out = (float*)d_out;

    pool_kernel<<<R1, 256>>>(x);
    gemm1_kernel<<<dim3(R1 / 128, H0 / 128), 256>>>(W_in, b_in);

    cudaFuncSetAttribute(step_all_kernel,
                         cudaFuncAttributeMaxDynamicSharedMemorySize, STEP_SMEM);
    step_all_kernel<<<NBLK, 256, STEP_SMEM>>>(W_hid, b_hid, beta_in, thr_in,
                                              beta_hid, thr_hid, W_out);
    out_all_kernel<<<1, BB * NCLS>>>(b_out, beta_out, out);
}

// round 8
// speedup vs baseline: 1.6973x; 1.0521x over previous
#include <cuda_runtime.h>

// ---------------- problem constants ----------------
#define BB    64
#define CC    3
#define NWIN  232
#define TT    8
#define CHUNK 29
#define DP    14
#define HP    16
#define WPOOL 16
#define NN    42            // CC*DP
#define FF    256           // HP*WPOOL
#define H0    256
#define H1    128
#define NCLS  6
#define R1    (TT*BB*NN)    // 21504 rows of cur_in_all
#define R2    (BB*NN)       // 2688 rows per timestep
#define NBLK  148           // persistent-shaped grid (one wave, 1 blk/SM)

typedef unsigned long long ull;

// ---------------- scratch (device globals; no mallocs allowed) -------------
__device__ float g_pr[(size_t)R1 * FF];             // pooled activations
__device__ float g_cur[(size_t)R1 * H0];            // cur_in_all (fc_in output)
__device__ float g_partial[(size_t)TT * R2 * NCLS]; // readout partials per step
__device__ float g_sums[TT * BB * NCLS];            // reduced per-(t,b,cls) sums

// ---------------- packed f32x2 helpers ----------------
__device__ __forceinline__ ull fma2(ull a, ull b, ull c) {
    asm("fma.rn.f32x2 %0, %1, %2, %0;" : "+l"(c) : "l"(a), "l"(b));
    return c;
}
__device__ __forceinline__ ull add2(ull a, ull b) {
    ull d;
    asm("add.rn.f32x2 %0, %1, %2;" : "=l"(d) : "l"(a), "l"(b));
    return d;
}
__device__ __forceinline__ ull dup2(float a) {
    unsigned u = __float_as_uint(a);
    ull d;
    asm("mov.b64 %0, {%1, %2};" : "=l"(d) : "r"(u), "r"(u));
    return d;
}

union F4U { float4 f; ull u[2]; float s[4]; };
union F2U { float2 f; ull u; float s[2]; };

__device__ __forceinline__ float clamp01(float v) {
    return fminf(fmaxf(v, 0.f), 1.f);
}

// ============================================================
// Kernel 1: avg-pool3d (2,2,2)/(2,2,2) VALID, fused reshape to (R1, 256)
// ============================================================
__global__ __launch_bounds__(256) void pool_kernel(const float* __restrict__ x) {
    int row = blockIdx.x;
    int f   = threadIdx.x;

    int t   = row / (BB * NN);
    int rem = row % (BB * NN);
    int b   = rem / NN;
    int n   = rem % NN;
    int c   = n / DP;
    int d   = n % DP;
    int hp  = f >> 4;
    int wp  = f & 15;

    const float2* x2 = (const float2*)x;
    long long base = ((long long)(b * CC + c) * NWIN + t * CHUNK + 2 * d) * 32;

    float s = 0.f;
    #pragma unroll
    for (int kd = 0; kd < 2; kd++) {
        #pragma unroll
        for (int kh = 0; kh < 2; kh++) {
            float2 v = x2[(base + (long long)kd * 32 + 2 * hp + kh) * 16 + wp];
            s += v.x + v.y;
        }
    }
    g_pr[(size_t)row * FF + f] = s * 0.125f;
}

// ============================================================
// Kernel 2: cur_in_all = pr @ W_in^T + b_in   (M=21504, N=256, K=256), fp32
// Double-buffered smem, occupancy 2; K-summation order identical to the
// previously-passing kernel (BK=16 chunks ascending) -> bitwise-same output.
// ============================================================
__global__ __launch_bounds__(256, 2) void gemm1_kernel(const float* __restrict__ Win,
                                                       const float* __restrict__ bin) {
    __shared__ float As[2][16 * 132];
    __shared__ float Bs[2][16 * 132];

    int tid = threadIdx.x;
    int m0 = blockIdx.x * 128;
    int n0 = blockIdx.y * 128;
    int tx = tid & 15;
    int ty = tid >> 4;

    // per-thread gmem staging (2 float4 of A, 2 of B per chunk)
    int r_[2], c4_[2];
    #pragma unroll
    for (int i = 0; i < 2; i++) {
        int idx = tid + i * 256;
        r_[i]  = idx >> 2;
        c4_[i] = (idx & 3) * 4;
    }

    ull acc[8][4];
    #pragma unroll
    for (int m = 0; m < 8; m++)
        #pragma unroll
        for (int nn = 0; nn < 4; nn++) acc[m][nn] = 0ull;

    float4 pa[2], pb[2];
    // prologue: load chunk 0
    #pragma unroll
    for (int i = 0; i < 2; i++) {
        pa[i] = *(const float4*)(g_pr + (size_t)(m0 + r_[i]) * FF + c4_[i]);
        pb[i] = *(const float4*)(Win + (size_t)(n0 + r_[i]) * H0 + c4_[i]);
    }
    #pragma unroll
    for (int i = 0; i < 2; i++) {
        int r = r_[i], c4 = c4_[i];
        As[0][(c4 + 0) * 132 + r] = pa[i].x;
        As[0][(c4 + 1) * 132 + r] = pa[i].y;
        As[0][(c4 + 2) * 132 + r] = pa[i].z;
        As[0][(c4 + 3) * 132 + r] = pa[i].w;
        Bs[0][(c4 + 0) * 132 + r] = pb[i].x;
        Bs[0][(c4 + 1) * 132 + r] = pb[i].y;
        Bs[0][(c4 + 2) * 132 + r] = pb[i].z;
        Bs[0][(c4 + 3) * 132 + r] = pb[i].w;
    }
    __syncthreads();

    for (int kc = 0; kc < 16; kc++) {
        int buf = kc & 1;
        if (kc < 15) {
            int k0 = (kc + 1) * 16;
            #pragma unroll
            for (int i = 0; i < 2; i++) {
                pa[i] = *(const float4*)(g_pr + (size_t)(m0 + r_[i]) * FF + k0 + c4_[i]);
                pb[i] = *(const float4*)(Win + (size_t)(n0 + r_[i]) * H0 + k0 + c4_[i]);
            }
        }

        #pragma unroll
        for (int kk = 0; kk < 16; kk++) {
            F4U a0, a1, b0, b1;
            a0.f = *(const float4*)&As[buf][kk * 132 + ty * 8];
            a1.f = *(const float4*)&As[buf][kk * 132 + ty * 8 + 4];
            b0.f = *(const float4*)&Bs[buf][kk * 132 + tx * 8];
            b1.f = *(const float4*)&Bs[buf][kk * 132 + tx * 8 + 4];
            ull bp[4] = { b0.u[0], b0.u[1], b1.u[0], b1.u[1] };
            float av[8] = { a0.s[0], a0.s[1], a0.s[2], a0.s[3],
                            a1.s[0], a1.s[1], a1.s[2], a1.s[3] };
            #pragma unroll
            for (int m = 0; m < 8; m++) {
                ull ad = dup2(av[m]);
                #pragma unroll
                for (int nn = 0; nn < 4; nn++)
                    acc[m][nn] = fma2(ad, bp[nn], acc[m][nn]);
            }
        }

        if (kc < 15) {
            int nb = buf ^ 1;
            #pragma unroll
            for (int i = 0; i < 2; i++) {
                int r = r_[i], c4 = c4_[i];
                As[nb][(c4 + 0) * 132 + r] = pa[i].x;
                As[nb][(c4 + 1) * 132 + r] = pa[i].y;
                As[nb][(c4 + 2) * 132 + r] = pa[i].z;
                As[nb][(c4 + 3) * 132 + r] = pa[i].w;
                Bs[nb][(c4 + 0) * 132 + r] = pb[i].x;
                Bs[nb][(c4 + 1) * 132 + r] = pb[i].y;
                Bs[nb][(c4 + 2) * 132 + r] = pb[i].z;
                Bs[nb][(c4 + 3) * 132 + r] = pb[i].w;
            }
            __syncthreads();
        }
    }

    F4U bi0, bi1;
    bi0.f = *(const float4*)(bin + n0 + tx * 8);
    bi1.f = *(const float4*)(bin + n0 + tx * 8 + 4);
    ull bp[4] = { bi0.u[0], bi0.u[1], bi1.u[0], bi1.u[1] };

    #pragma unroll
    for (int m = 0; m < 8; m++) {
        F4U o0, o1;
        o0.u[0] = add2(acc[m][0], bp[0]);
        o0.u[1] = add2(acc[m][1], bp[1]);
        o1.u[0] = add2(acc[m][2], bp[2]);
        o1.u[1] = add2(acc[m][3], bp[3]);
        float* outp = g_cur + (size_t)(m0 + ty * 8 + m) * H0 + n0 + tx * 8;
        *(float4*)outp = o0.f;
        *(float4*)(outp + 4) = o1.f;
    }
}

// ============================================================
// Kernel 3: ALL 8 timesteps fused in one persistent kernel.
// ============================================================
#define SROWS 20
#define WROW  130
#define SMEM_W_BYTES     (257 * WROW * 4)
#define SMEM_SPK2_OFF    SMEM_W_BYTES
#define SMEM_LST_OFF     (SMEM_SPK2_OFF + SROWS * H1 * 4)
#define SMEM_CNT_OFF     (SMEM_LST_OFF + SROWS * 256 * 2)
#define STEP_SMEM        (SMEM_CNT_OFF + SROWS * 4)

__global__ __launch_bounds__(256) void step_all_kernel(
    const float* __restrict__ W_hid, const float* __restrict__ b_hid,
    const float* __restrict__ beta_in, const float* __restrict__ thr_in,
    const float* __restrict__ beta_hid, const float* __restrict__ thr_hid,
    const float* __restrict__ W_out)
{
    extern __shared__ char smem[];
    float*          sW    = (float*)smem;
    float*          sSpk2 = (float*)(smem + SMEM_SPK2_OFF);
    unsigned short* sLst  = (unsigned short*)(smem + SMEM_LST_OFF);
    int*            sCnt  = (int*)(smem + SMEM_CNT_OFF);

    int tid  = threadIdx.x;
    int lane = tid & 31;
    int warp = tid >> 5;
    int r0 = (int)(((long long)blockIdx.x * R2) / NBLK);
    int r1 = (int)(((long long)(blockIdx.x + 1) * R2) / NBLK);

    // ---- stage W_hid transposed (k-major) + zero sentinel row, ONCE ----
    #pragma unroll 4
    for (int g = 0; g < H1; g++)
        sW[tid * WROW + g] = W_hid[g * H0 + tid];   // tid == k
    if (tid < H1) sW[256 * WROW + tid] = 0.f;

    // ---- hoisted LIF1 params + register-resident mem_in ----
    float thrA[8], betA[8];
    #pragma unroll
    for (int kb = 0; kb < 8; kb++) {
        int k = kb * 32 + lane;
        thrA[kb] = thr_in[k];
        betA[kb] = clamp01(beta_in[k]);
    }
    float memA[3][8];
    #pragma unroll
    for (int ri = 0; ri < 3; ri++)
        #pragma unroll
        for (int kb = 0; kb < 8; kb++) memA[ri][kb] = 0.f;

    // ---- hoisted LIF2 params + register-resident mem_hid ----
    int j = tid & 63;       // g-pair
    int q = tid >> 6;       // row-within-chunk
    const ull* sW2 = (const ull*)sW;
    F2U bh;  bh.f  = *(const float2*)(b_hid    + 2 * j);
    float2 bhf     = *(const float2*)(beta_hid + 2 * j);
    float betx = clamp01(bhf.x), bety = clamp01(bhf.y);
    float2 thh     = *(const float2*)(thr_hid  + 2 * j);
    float2 memh[5];
    #pragma unroll
    for (int c = 0; c < 5; c++) memh[c] = make_float2(0.f, 0.f);

    unsigned lmask = (1u << lane) - 1u;
    __syncthreads();

    for (int t = 0; t < TT; t++) {
        // ---- phase 1: LIF1 + warp-ballot compaction of active h per row ----
        #pragma unroll
        for (int ri = 0; ri < 3; ri++) {
            int rl = warp + ri * 8;
            if (rl < SROWS) {
                int row = r0 + rl;
                if (row < r1) {
                    int cnt = 0;
                    unsigned short* lst = sLst + rl * 256;
                    const float* curp = g_cur + ((size_t)t * R2 + row) * H0;
                    #pragma unroll
                    for (int kb = 0; kb < 8; kb++) {
                        float mem = memA[ri][kb];
                        float cur = curp[kb * 32 + lane];
                        float rst = (mem > thrA[kb]) ? thrA[kb] : 0.f;
                        mem = fmaf(betA[kb], mem, cur) - rst;
                        memA[ri][kb] = mem;
                        int s = (mem - thrA[kb] > 0.f) ? 1 : 0;
                        unsigned bal = __ballot_sync(0xffffffffu, s);
                        if (s) lst[cnt + __popc(bal & lmask)] =
                                   (unsigned short)(kb * 32 + lane);
                        cnt += __popc(bal);
                    }
                    int cnt4 = (cnt + 3) & ~3;
                    if (lane < cnt4 - cnt) lst[cnt + lane] = 256;  // zero-row pad
                    if (lane == 0) sCnt[rl] = cnt4;
                } else if (lane == 0) {
                    sCnt[rl] = 0;
                }
            }
        }
        __syncthreads();

        // ---- phase 2+3: hidden current (compacted adds) + LIF2 ----
        #pragma unroll
        for (int c = 0; c < 5; c++) {
            int rl = c * 4 + q;
            int cnt4 = sCnt[rl];
            const unsigned short* lst = sLst + rl * 256;
            ull acc0 = bh.u;
            ull acc1 = 0ull;
            for (int i = 0; i < cnt4; i += 4) {
                ushort4 kk = *(const ushort4*)(lst + i);
                acc0 = add2(acc0, sW2[(int)kk.x * 65 + j]);
                acc1 = add2(acc1, sW2[(int)kk.y * 65 + j]);
                acc0 = add2(acc0, sW2[(int)kk.z * 65 + j]);
                acc1 = add2(acc1, sW2[(int)kk.w * 65 + j]);
            }
            ull accs = add2(acc0, acc1);

            int row = r0 + rl;
            if (row < r1) {
                F2U a; a.u = accs;
                float2 mem = memh[c];
                float rx = (mem.x > thh.x) ? thh.x : 0.f;
                float ry = (mem.y > thh.y) ? thh.y : 0.f;
                mem.x = fmaf(betx, mem.x, a.s[0]) - rx;
                mem.y = fmaf(bety, mem.y, a.s[1]) - ry;
                memh[c] = mem;
                float2 sp;
                sp.x = (mem.x - thh.x > 0.f) ? 1.f : 0.f;
                sp.y = (mem.y - thh.y > 0.f) ? 1.f : 0.f;
                *(float2*)(sSpk2 + rl * H1 + 2 * j) = sp;
            }
        }
        __syncthreads();

        // ---- phase 4: per-row readout partials (fixed-order reduce) ----
        for (int rl = warp; rl < SROWS; rl += 8) {
            int row = r0 + rl;
            if (row >= r1) continue;
            int n = row % NN;
            const float* wo = W_out + n * H1;
            float sv[4];
            #pragma unroll
            for (int gi = 0; gi < 4; gi++) sv[gi] = sSpk2[rl * H1 + gi * 32 + lane];
            #pragma unroll
            for (int cls = 0; cls < NCLS; cls++) {
                float p = 0.f;
                #pragma unroll
                for (int gi = 0; gi < 4; gi++)
                    p = fmaf(wo[cls * (NN * H1) + gi * 32 + lane], sv[gi], p);
                #pragma unroll
                for (int off = 16; off; off >>= 1)
                    p += __shfl_down_sync(0xffffffffu, p, off);
                if (lane == 0)
                    g_partial[((size_t)t * R2 + row) * NCLS + cls] = p;
            }
        }
    }
}

// ============================================================
// Kernel 4a: per-(t,b,cls) partial reduction, parallel across 12 blocks.
// Summation order identical (sequential over n ascending) -> bitwise same.
// ============================================================
__global__ __launch_bounds__(256) void out_reduce_kernel(const float* __restrict__ b_out)
{
    int g = blockIdx.x * 256 + threadIdx.x;     // 0..3071
    if (g >= TT * BB * NCLS) return;
    int t  = g / (BB * NCLS);
    int r  = g % (BB * NCLS);
    int b  = r / NCLS;
    int cls = r % NCLS;

    float s = b_out[cls];
    const float* pp = g_partial + ((size_t)t * R2 + (size_t)b * NN) * NCLS + cls;
    #pragma unroll
    for (int n = 0; n < NN; n++) s += pp[n * NCLS];
    g_sums[t * (BB * NCLS) + r] = s;
}

// ============================================================
// Kernel 4b: 8-step output-LIF chain (trivial).
// ============================================================
__global__ __launch_bounds__(BB * NCLS) void out_chain_kernel(
    const float* __restrict__ beta_out, float* __restrict__ out)
{
    int tid = threadIdx.x;                 // 0..383
    int cls = tid % NCLS;
    float beta = clamp01(beta_out[cls]);

    float sums[TT];
    #pragma unroll
    for (int t = 0; t < TT; t++) sums[t] = g_sums[t * (BB * NCLS) + tid];

    float mem = 0.f;
    #pragma unroll
    for (int t = 0; t < TT; t++) {
        float rst = (mem > 1.f) ? 1.f : 0.f;
        mem = fmaf(beta, mem, sums[t]) - rst;
        out[t * (BB * NCLS) + tid] = (mem - 1.f > 0.f) ? 1.f : 0.f;
    }
}

// ============================================================
// launch
// ============================================================
extern "C" void kernel_launch(void* const* d_in, const int* in_sizes, int n_in,
                              void* d_out, int out_size) {
    (void)in_sizes; (void)n_in; (void)out_size;
    const float* x        = (const float*)d_in[0];
    const float* W_in     = (const float*)d_in[1];
    const float* b_in     = (const float*)d_in[2];
    const float* W_hid    = (const float*)d_in[3];
    const float* b_hid    = (const float*)d_in[4];
    const float* W_out    = (const float*)d_in[5];
    const float* b_out    = (const float*)d_in[6];
    const float* beta_in  = (const float*)d_in[7];
    const float* thr_in   = (const float*)d_in[8];
    const float* beta_hid = (const float*)d_in[9];
    const float* thr_hid  = (const float*)d_in[10];
    const float* beta_out = (const float*)d_in[11];
    float* out = (float*)d_out;

    pool_kernel<<<R1, 256>>>(x);
    gemm1_kernel<<<dim3(R1 / 128, H0 / 128), 256>>>(W_in, b_in);

    cudaFuncSetAttribute(step_all_kernel,
                         cudaFuncAttributeMaxDynamicSharedMemorySize, STEP_SMEM);
    step_all_kernel<<<NBLK, 256, STEP_SMEM>>>(W_hid, b_hid, beta_in, thr_in,
                                              beta_hid, thr_hid, W_out);
    out_reduce_kernel<<<12, 256>>>(b_out);
    out_chain_kernel<<<1, BB * NCLS>>>(beta_out, out);
}